// round 16
// baseline (speedup 1.0000x reference)
#include <cuda_runtime.h>
#include <math.h>
#include <limits.h>
#include <stdint.h>

// ---------------- problem shape ----------------
#define B_      64
#define TOK     50
#define P_PER_B 49
#define NP      3136
#define NP_PAD  3200      // 25 * 128
#define D_      768
#define NM      100000
#define NM_PAD  100096    // 782 * 128
#define NGRP    3128      // 32-col groups (overflow fallback only)
#define CAP     192       // per-patch candidate list capacity

// ---------------- GEMM tiling (frozen R8/R14) ----
#define BM 128
#define BN 128
#define KCB 128
#define NCHUNK 6
#define NTHR 256          // 8 warps: 2(M) x 4(N), warp tile 64x32

// SMEM: 3 stages x (A 16KB + B 16KB) = 96KB, then scalars
#define SM_A(s) ((s) * 16384)
#define SM_B(s) (49152 + (s) * 16384)
#define SM_SA   98304     // 128 f32
#define SM_C1   98816
#define SM_BIAS 99328
#define SM_RED  99840     // 128*4 u32 = 2048
#define SM_GATE 101888    // 128 f32
#define SM_TOTAL (101888 + 512)   // 102400 B

#define MARGIN 4.0e-3f

// ---------------- scratch ----------------------
__device__ int8_t g_pA8[(size_t)NP_PAD * D_];
__device__ int8_t g_mbB8[(size_t)NM_PAD * D_];
__device__ float  g_pN[(size_t)NP * D_];
__device__ float  g_sa[NP_PAD];
__device__ float  g_c1[NM_PAD];
__device__ float  g_inv[NM_PAD];
__device__ float  g_bias[NM_PAD];
__device__ float  g_p2[NP];
__device__ unsigned int g_maxq[NP_PAD];             // encoded per-patch quantized max
__device__ int    g_cnt[NP];                        // candidate list counters
__device__ unsigned long long g_list[(size_t)NP * CAP];  // (key<<32)|column
__device__ int    g_maxv[NP];

// ---------------- helpers ----------------------
__device__ __forceinline__ int f2ord(float f) {
    int i = __float_as_int(f);
    return (i >= 0) ? i : (i ^ 0x7FFFFFFF);
}
__device__ __forceinline__ float ord2f(int i) {
    return __int_as_float((i >= 0) ? i : (i ^ 0x7FFFFFFF));
}
__device__ __forceinline__ uint32_t enc(float v) { return (uint32_t)f2ord(v) ^ 0x80000000u; }
__device__ __forceinline__ float dec(uint32_t k) { return ord2f((int)(k ^ 0x80000000u)); }

__device__ __forceinline__ uint32_t smem_u32(const void* p) {
    uint32_t a;
    asm("{ .reg .u64 t; cvta.to.shared.u64 t, %1; cvt.u32.u64 %0, t; }" : "=r"(a) : "l"(p));
    return a;
}
__device__ __forceinline__ void cp_async16(uint32_t dst, const void* src) {
    asm volatile("cp.async.cg.shared.global [%0], [%1], 16;" :: "r"(dst), "l"(src));
}
#define CP_COMMIT() asm volatile("cp.async.commit_group;" ::: "memory")
#define CP_WAIT0()  asm volatile("cp.async.wait_group 0;" ::: "memory")
#define CP_WAIT1()  asm volatile("cp.async.wait_group 1;" ::: "memory")

__device__ __forceinline__ uint32_t sw128(uint32_t off) {
    return off ^ ((off >> 3) & 0x70);
}
__device__ __forceinline__ void ldmat_x4(uint32_t* r, uint32_t addr) {
    asm volatile("ldmatrix.sync.aligned.m8n8.x4.shared.b16 {%0,%1,%2,%3}, [%4];"
        : "=r"(r[0]), "=r"(r[1]), "=r"(r[2]), "=r"(r[3]) : "r"(addr));
}
__device__ __forceinline__ void imma16832(int* c, const uint32_t* a, const uint32_t* b) {
    asm volatile("mma.sync.aligned.m16n8k32.row.col.s32.s8.s8.s32 "
        "{%0,%1,%2,%3}, {%4,%5,%6,%7}, {%8,%9}, {%0,%1,%2,%3};"
        : "+r"(c[0]), "+r"(c[1]), "+r"(c[2]), "+r"(c[3])
        : "r"(a[0]), "r"(a[1]), "r"(a[2]), "r"(a[3]), "r"(b[0]), "r"(b[1]));
}
__device__ __forceinline__ int8_t q8(float v, float rq) {
    int q = __float2int_rn(v * rq);
    q = max(-127, min(127, q));
    return (int8_t)q;
}

// ---------------- kernel 1: normalize patches + reset state ----------------
__global__ void norm_patches_kernel(const float* __restrict__ tokens) {
    int pb = blockIdx.x, tid = threadIdx.x;
    if (tid == 0) {
        g_maxq[pb] = 0u;
        if (pb < NP) g_cnt[pb] = 0;
    }
    int8_t* dst8 = g_pA8 + (size_t)pb * D_;
    if (pb >= NP) {
        dst8[tid] = 0; dst8[tid + 256] = 0; dst8[tid + 512] = 0;
        if (tid == 0) g_sa[pb] = 0.0f;
        return;
    }
    int b = pb / P_PER_B, j = pb % P_PER_B;
    const float* src = tokens + ((size_t)(b * TOK + 1 + j)) * D_;
    float v0 = src[tid], v1 = src[tid + 256], v2 = src[tid + 512];
    float s = v0 * v0 + v1 * v1 + v2 * v2;
    float a = fmaxf(fabsf(v0), fmaxf(fabsf(v1), fabsf(v2)));

    __shared__ float ws[8], wa[8];
    __shared__ float s_tot, s_amax;
    #pragma unroll
    for (int o = 16; o; o >>= 1) {
        s += __shfl_xor_sync(0xFFFFFFFFu, s, o);
        a = fmaxf(a, __shfl_xor_sync(0xFFFFFFFFu, a, o));
    }
    if ((tid & 31) == 0) { ws[tid >> 5] = s; wa[tid >> 5] = a; }
    __syncthreads();
    if (tid < 32) {
        float t = (tid < 8) ? ws[tid] : 0.0f;
        float m = (tid < 8) ? wa[tid] : 0.0f;
        #pragma unroll
        for (int o = 4; o; o >>= 1) {
            t += __shfl_xor_sync(0xFFFFFFFFu, t, o);
            m = fmaxf(m, __shfl_xor_sync(0xFFFFFFFFu, m, o));
        }
        if (tid == 0) { s_tot = t; s_amax = m; }
    }
    __syncthreads();
    float tot = s_tot;
    float inv = 1.0f / (sqrtf(tot) + 1e-12f);
    float amax_n = s_amax * inv;
    float rq = (amax_n > 0.0f) ? (127.0f / amax_n) : 0.0f;

    float* pn = g_pN + (size_t)pb * D_;
    float n0 = v0 * inv, n1 = v1 * inv, n2 = v2 * inv;
    pn[tid] = n0; pn[tid + 256] = n1; pn[tid + 512] = n2;
    dst8[tid]       = q8(n0, rq);
    dst8[tid + 256] = q8(n1, rq);
    dst8[tid + 512] = q8(n2, rq);
    if (tid == 0) {
        g_sa[pb] = amax_n / 127.0f;
        g_p2[pb] = tot * inv * inv;
    }
}

// ---------------- kernel 2: MB stats + int8 quantize ------------------------
__global__ void mb_convert_kernel(const float* __restrict__ mb) {
    int row  = blockIdx.x * 8 + (threadIdx.x >> 5);
    int lane = threadIdx.x & 31;
    if (row >= NM_PAD) return;
    uint32_t* dst = (uint32_t*)(g_mbB8 + (size_t)row * D_);
    if (row < NM) {
        const float4* r = (const float4*)(mb + (size_t)row * D_);
        float4 v[6]; float s = 0.0f, a = 0.0f;
        #pragma unroll
        for (int i = 0; i < 6; i++) {
            v[i] = r[lane + i * 32];
            s += v[i].x * v[i].x + v[i].y * v[i].y + v[i].z * v[i].z + v[i].w * v[i].w;
            a = fmaxf(a, fmaxf(fmaxf(fabsf(v[i].x), fabsf(v[i].y)),
                               fmaxf(fabsf(v[i].z), fabsf(v[i].w))));
        }
        #pragma unroll
        for (int o = 16; o; o >>= 1) {
            s += __shfl_xor_sync(0xFFFFFFFFu, s, o);
            a = fmaxf(a, __shfl_xor_sync(0xFFFFFFFFu, a, o));
        }
        float rq = (a > 0.0f) ? (127.0f / a) : 0.0f;
        #pragma unroll
        for (int i = 0; i < 6; i++) {
            uint32_t w = ((uint32_t)(uint8_t)q8(v[i].x, rq))
                       | ((uint32_t)(uint8_t)q8(v[i].y, rq) << 8)
                       | ((uint32_t)(uint8_t)q8(v[i].z, rq) << 16)
                       | ((uint32_t)(uint8_t)q8(v[i].w, rq) << 24);
            dst[lane + i * 32] = w;
        }
        if (lane == 0) {
            float inv = 1.0f / (sqrtf(s) + 1e-12f);
            g_inv[row]  = inv;
            g_bias[row] = 0.5f * s * inv * inv;
            g_c1[row]   = (a / 127.0f) * inv;
        }
    } else {
        #pragma unroll
        for (int i = 0; i < 6; i++) dst[lane + i * 32] = 0u;
        if (lane == 0) { g_inv[row] = 0.0f; g_bias[row] = 1e30f; g_c1[row] = 0.0f; }
    }
}

// ---------------- kernel 3: IMMA GEMM + per-COLUMN gated append -------------
__global__ void __launch_bounds__(NTHR, 2)
gemm_imma_kernel() {
    extern __shared__ __align__(1024) char smem[];
    const uint32_t sbase = smem_u32(smem);
    const int tid  = threadIdx.x;
    const int wid  = tid >> 5;
    const int lane = tid & 31;
    const int p0 = blockIdx.x * BM;
    const int n0 = blockIdx.y * BN;
    const int wm = (wid & 1) * 64;
    const int wn_idx = wid >> 1;
    const int wn = wn_idx * 32;
    const int g  = lane >> 2;
    const int tq = lane & 3;

    float* sa_s   = (float*)(smem + SM_SA);
    float* c1_s   = (float*)(smem + SM_C1);
    float* bias_s = (float*)(smem + SM_BIAS);
    uint32_t* red = (uint32_t*)(smem + SM_RED);    // [128 rows][4 groups]
    float* gate_s = (float*)(smem + SM_GATE);      // [128 rows]

    if (tid < 128) {
        sa_s[tid]   = g_sa[p0 + tid];
        c1_s[tid]   = g_c1[n0 + tid];
        bias_s[tid] = g_bias[n0 + tid];
    }

    const int8_t* gA = g_pA8  + (size_t)p0 * D_;
    const int8_t* gB = g_mbB8 + (size_t)n0 * D_;
    const int ld_r = tid >> 3;
    const int ld_c = tid & 7;
    const uint32_t ld_off0 = sw128((uint32_t)(ld_r * 128 + ld_c * 16));
    const uint32_t ld_off1 = sw128((uint32_t)((ld_r + 32) * 128 + ld_c * 16));
    const uint32_t ld_off2 = sw128((uint32_t)((ld_r + 64) * 128 + ld_c * 16));
    const uint32_t ld_off3 = sw128((uint32_t)((ld_r + 96) * 128 + ld_c * 16));

    // prologue: chunks 0,1 -> stages 0,1
    #pragma unroll
    for (int pc = 0; pc < 2; pc++) {
        const int8_t* cA = gA + (size_t)pc * KCB;
        const int8_t* cB = gB + (size_t)pc * KCB;
        const uint32_t dA = sbase + SM_A(pc);
        const uint32_t dB = sbase + SM_B(pc);
        const size_t ga0 = (size_t)ld_r * D_ + ld_c * 16;
        cp_async16(dA + ld_off0, cA + ga0);
        cp_async16(dA + ld_off1, cA + ga0 + (size_t)32 * D_);
        cp_async16(dA + ld_off2, cA + ga0 + (size_t)64 * D_);
        cp_async16(dA + ld_off3, cA + ga0 + (size_t)96 * D_);
        cp_async16(dB + ld_off0, cB + ga0);
        cp_async16(dB + ld_off1, cB + ga0 + (size_t)32 * D_);
        cp_async16(dB + ld_off2, cB + ga0 + (size_t)64 * D_);
        cp_async16(dB + ld_off3, cB + ga0 + (size_t)96 * D_);
        CP_COMMIT();
    }

    const uint32_t aRow = (uint32_t)(wm + (lane & 15)) * 128;
    const uint32_t aCol = (uint32_t)((lane >> 4) << 4);
    const uint32_t bRow = (uint32_t)(wn + (lane & 7) + ((lane >> 4) << 3)) * 128;
    const uint32_t bCol = (uint32_t)(((lane >> 3) & 1) << 4);

    int acc[4][4][4];
    #pragma unroll
    for (int i = 0; i < 4; i++)
        #pragma unroll
        for (int j = 0; j < 4; j++)
            #pragma unroll
            for (int q = 0; q < 4; q++) acc[i][j][q] = 0;

    #pragma unroll 1
    for (int kc = 0; kc < NCHUNK; kc++) {
        const int s = kc % 3;
        const uint32_t sA = sbase + SM_A(s);
        const uint32_t sB = sbase + SM_B(s);

        if (kc + 1 < NCHUNK) { CP_WAIT1(); } else { CP_WAIT0(); }
        __syncthreads();

        if (kc + 2 < NCHUNK) {
            const int d = (kc + 2) % 3;
            const uint32_t dA = sbase + SM_A(d);
            const uint32_t dB = sbase + SM_B(d);
            const int8_t* cA = gA + (size_t)(kc + 2) * KCB;
            const int8_t* cB = gB + (size_t)(kc + 2) * KCB;
            const size_t ga0 = (size_t)ld_r * D_ + ld_c * 16;
            cp_async16(dA + ld_off0, cA + ga0);
            cp_async16(dA + ld_off1, cA + ga0 + (size_t)32 * D_);
            cp_async16(dA + ld_off2, cA + ga0 + (size_t)64 * D_);
            cp_async16(dA + ld_off3, cA + ga0 + (size_t)96 * D_);
            cp_async16(dB + ld_off0, cB + ga0);
            cp_async16(dB + ld_off1, cB + ga0 + (size_t)32 * D_);
            cp_async16(dB + ld_off2, cB + ga0 + (size_t)64 * D_);
            cp_async16(dB + ld_off3, cB + ga0 + (size_t)96 * D_);
            CP_COMMIT();
        }

        #pragma unroll
        for (int ks = 0; ks < 4; ks++) {
            const uint32_t kb = (uint32_t)(ks * 32);
            uint32_t af[4][4], bf[2][4];
            #pragma unroll
            for (int tm = 0; tm < 4; tm++)
                ldmat_x4(af[tm], sA + sw128(aRow + (uint32_t)(tm * 16 * 128) + kb + aCol));
            #pragma unroll
            for (int bn = 0; bn < 2; bn++)
                ldmat_x4(bf[bn], sB + sw128(bRow + (uint32_t)(bn * 16 * 128) + kb + bCol));
            #pragma unroll
            for (int tm = 0; tm < 4; tm++)
                #pragma unroll
                for (int tn = 0; tn < 4; tn++)
                    imma16832(acc[tm][tn], af[tm], bf[tn >> 1] + (tn & 1) * 2);
        }
    }
    __syncthreads();

    // ---- epilogue phase 1: per-row max (value only) ----
    #pragma unroll
    for (int tm = 0; tm < 4; tm++) {
        #pragma unroll
        for (int half = 0; half < 2; half++) {
            int rl = wm + tm * 16 + g + half * 8;
            float sar = sa_s[rl];
            float best = -3.0e38f;
            #pragma unroll
            for (int tn = 0; tn < 4; tn++) {
                int cl = wn + tn * 8 + tq * 2;
                float v0 = (float)acc[tm][tn][half * 2 + 0] * (sar * c1_s[cl])     - bias_s[cl];
                float v1 = (float)acc[tm][tn][half * 2 + 1] * (sar * c1_s[cl + 1]) - bias_s[cl + 1];
                best = fmaxf(best, fmaxf(v0, v1));
            }
            best = fmaxf(best, __shfl_xor_sync(0xFFFFFFFFu, best, 1));
            best = fmaxf(best, __shfl_xor_sync(0xFFFFFFFFu, best, 2));
            if (tq == 0) red[rl * 4 + wn_idx] = enc(best);
        }
    }
    __syncthreads();

    // per-row: ONE atomicMax; publish gate value for phase 2
    if (tid < 128) {
        int p = p0 + tid;
        float gatev = 3.0e38f;           // padding rows: gate passes nothing
        if (p < NP) {
            uint32_t k0 = red[tid * 4 + 0];
            uint32_t k1 = red[tid * 4 + 1];
            uint32_t k2 = red[tid * 4 + 2];
            uint32_t k3 = red[tid * 4 + 3];
            uint32_t rowmax = max(max(k0, k1), max(k2, k3));
            uint32_t old = atomicMax(&g_maxq[p], rowmax);
            gatev = dec(max(old, rowmax)) - MARGIN;
        }
        gate_s[tid] = gatev;
    }
    __syncthreads();

    // ---- epilogue phase 2: per-COLUMN gated append (values from registers) --
    #pragma unroll
    for (int tm = 0; tm < 4; tm++) {
        #pragma unroll
        for (int half = 0; half < 2; half++) {
            int rl = wm + tm * 16 + g + half * 8;
            float sar  = sa_s[rl];
            float gate = gate_s[rl];
            int p = p0 + rl;
            #pragma unroll
            for (int tn = 0; tn < 4; tn++) {
                int cl = wn + tn * 8 + tq * 2;
                float v0 = (float)acc[tm][tn][half * 2 + 0] * (sar * c1_s[cl])     - bias_s[cl];
                float v1 = (float)acc[tm][tn][half * 2 + 1] * (sar * c1_s[cl + 1]) - bias_s[cl + 1];
                if (v0 >= gate) {
                    int ix = atomicAdd(&g_cnt[p], 1);
                    if (ix < CAP)
                        g_list[(size_t)p * CAP + ix] =
                            ((unsigned long long)enc(v0) << 32) | (uint32_t)(n0 + cl);
                }
                if (v1 >= gate) {
                    int ix = atomicAdd(&g_cnt[p], 1);
                    if (ix < CAP)
                        g_list[(size_t)p * CAP + ix] =
                            ((unsigned long long)enc(v1) << 32) | (uint32_t)(n0 + cl + 1);
                }
            }
        }
    }
}

// ---------------- kernel 4: rescore — exact fp32 on listed columns ----------
__global__ void __launch_bounds__(128)
rescore_kernel(const float* __restrict__ mb) {
    __shared__ int s_cols[64];
    __shared__ int s_ccnt;
    __shared__ float s_best[4];

    const int p = blockIdx.x;
    const int tid = threadIdx.x;
    const int wid = tid >> 5;
    const int lane = tid & 31;

    const float thr = dec(g_maxq[p]) - MARGIN;
    const uint32_t thrkey = enc(thr);
    const int cnt = g_cnt[p];
    const bool overflow = (cnt > CAP);
    if (tid == 0) s_ccnt = 0;
    __syncthreads();

    if (!overflow) {
        // collect surviving columns directly from the list
        const unsigned long long* lst = g_list + (size_t)p * CAP;
        for (int e = tid; e < cnt; e += 128) {
            unsigned long long v = lst[e];
            if ((uint32_t)(v >> 32) >= thrkey) {
                int ix = atomicAdd(&s_ccnt, 1);
                if (ix < 64) s_cols[ix] = (int)(uint32_t)v;
            }
        }
        __syncthreads();
    } else {
        // fallback (statistically never): dp4a full scan over all groups
        const float sa = g_sa[p];
        int paw[6];
        const int* pa = (const int*)(g_pA8 + (size_t)p * D_);
        #pragma unroll
        for (int i = 0; i < 6; i++) paw[i] = pa[lane + i * 32];
        for (int base = wid * 8; base < NGRP * 32; base += 32) {
            int acc8[8]; int col8[8];
            #pragma unroll
            for (int j = 0; j < 8; j++) {
                int idx = base + j;
                col8[j] = idx;
                acc8[j] = 0;
                const int* bc = (const int*)(g_mbB8 + (size_t)idx * D_);
                #pragma unroll
                for (int i = 0; i < 6; i++)
                    acc8[j] = __dp4a(paw[i], bc[lane + i * 32], acc8[j]);
            }
            #pragma unroll
            for (int j = 0; j < 8; j++) {
                int dot = __reduce_add_sync(0xFFFFFFFFu, acc8[j]);
                if (lane == 0) {
                    int col = col8[j];
                    float vq = (float)dot * sa * g_c1[col] - g_bias[col];
                    if (vq >= thr) {
                        int ix = atomicAdd(&s_ccnt, 1);
                        if (ix < 64) s_cols[ix] = col;
                    }
                }
            }
        }
        __syncthreads();
    }
    const int nc = min(s_ccnt, 64);

    // exact fp32 rescore of surviving columns (warp per column)
    float pnw[24];
    {
        const float* pn = g_pN + (size_t)p * D_;
        #pragma unroll
        for (int i = 0; i < 24; i++) pnw[i] = pn[lane + i * 32];
    }
    float bestE = -3.0e38f;
    for (int ic = wid; ic < nc; ic += 4) {
        int col = s_cols[ic];
        const float* mcol = mb + (size_t)col * D_;
        float dot = 0.0f;
        #pragma unroll
        for (int i = 0; i < 24; i++) dot += pnw[i] * mcol[lane + i * 32];
        #pragma unroll
        for (int o = 16; o; o >>= 1) dot += __shfl_xor_sync(0xFFFFFFFFu, dot, o);
        bestE = fmaxf(bestE, dot * g_inv[col] - g_bias[col]);
    }
    if (lane == 0) s_best[wid] = bestE;
    __syncthreads();
    if (tid == 0) {
        float m = fmaxf(fmaxf(s_best[0], s_best[1]), fmaxf(s_best[2], s_best[3]));
        g_maxv[p] = f2ord(m);
    }
}

// ---------------- kernel 5: finalize ----------------------------------------
__global__ void finalize_kernel(float* __restrict__ out) {
    int b = threadIdx.x;
    if (b >= B_) return;
    float mx = -3.0e38f;
    #pragma unroll 7
    for (int j = 0; j < P_PER_B; j++) {
        int p = b * P_PER_B + j;
        float v  = ord2f(g_maxv[p]);
        float d2 = g_p2[p] - 2.0f * v;
        mx = fmaxf(mx, d2);
    }
    out[b] = sqrtf(fmaxf(mx, 1e-12f));
}

// ---------------- launch -----------------------------------------------------
extern "C" void kernel_launch(void* const* d_in, const int* in_sizes, int n_in,
                              void* d_out, int out_size) {
    (void)in_sizes; (void)n_in; (void)out_size;
    const float* tokens = (const float*)d_in[0];
    const float* mb     = (const float*)d_in[1];
    float* out          = (float*)d_out;

    norm_patches_kernel<<<NP_PAD, 256>>>(tokens);
    mb_convert_kernel<<<NM_PAD / 8, 256>>>(mb);

    cudaFuncSetAttribute(gemm_imma_kernel,
                         cudaFuncAttributeMaxDynamicSharedMemorySize, SM_TOTAL);
    dim3 grid(NP_PAD / BM, NM_PAD / BN);   // (25, 782)
    gemm_imma_kernel<<<grid, NTHR, SM_TOTAL>>>();

    rescore_kernel<<<NP, 128>>>(mb);
    finalize_kernel<<<1, 64>>>(out);
}

// round 17
// speedup vs baseline: 1.0693x; 1.0693x over previous
#include <cuda_runtime.h>
#include <math.h>
#include <limits.h>
#include <stdint.h>

// ---------------- problem shape ----------------
#define B_      64
#define TOK     50
#define P_PER_B 49
#define NP      3136
#define NP_PAD  3200      // 25 * 128
#define D_      768
#define NM      100000
#define NM_PAD  100096    // 782 * 128
#define NGRP    3128      // 32-col groups (overflow fallback only)
#define CAP     192       // per-patch candidate list capacity

// ---------------- GEMM tiling (frozen R8/R14) ----
#define BM 128
#define BN 128
#define KCB 128
#define NCHUNK 6
#define NTHR 256          // 8 warps: 2(M) x 4(N), warp tile 64x32

// SMEM: 3 stages x (A 16KB + B 16KB) = 96KB, then scalars
#define SM_A(s) ((s) * 16384)
#define SM_B(s) (49152 + (s) * 16384)
#define SM_SA   98304     // 128 f32
#define SM_C1   98816
#define SM_BIAS 99328
#define SM_RED  99840     // 128*4 u32 = 2048
#define SM_GATE 101888    // 128 f32
#define SM_TOTAL (101888 + 512)   // 102400 B

#define MARGIN 4.0e-3f

// ---------------- scratch ----------------------
__device__ int8_t g_pA8[(size_t)NP_PAD * D_];
__device__ int8_t g_mbB8[(size_t)NM_PAD * D_];
__device__ float  g_pN[(size_t)NP * D_];
__device__ float  g_sa[NP_PAD];
__device__ float  g_c1[NM_PAD];
__device__ float  g_inv[NM_PAD];
__device__ float  g_bias[NM_PAD];
__device__ float  g_p2[NP];
__device__ unsigned int g_maxq[NP_PAD];             // encoded per-patch quantized max
__device__ int    g_cnt[NP];                        // candidate list counters
__device__ unsigned long long g_list[(size_t)NP * CAP];  // (key<<32)|column
__device__ int    g_maxv[NP];

// ---------------- helpers ----------------------
__device__ __forceinline__ int f2ord(float f) {
    int i = __float_as_int(f);
    return (i >= 0) ? i : (i ^ 0x7FFFFFFF);
}
__device__ __forceinline__ float ord2f(int i) {
    return __int_as_float((i >= 0) ? i : (i ^ 0x7FFFFFFF));
}
__device__ __forceinline__ uint32_t enc(float v) { return (uint32_t)f2ord(v) ^ 0x80000000u; }
__device__ __forceinline__ float dec(uint32_t k) { return ord2f((int)(k ^ 0x80000000u)); }

__device__ __forceinline__ uint32_t smem_u32(const void* p) {
    uint32_t a;
    asm("{ .reg .u64 t; cvta.to.shared.u64 t, %1; cvt.u32.u64 %0, t; }" : "=r"(a) : "l"(p));
    return a;
}
__device__ __forceinline__ void cp_async16(uint32_t dst, const void* src) {
    asm volatile("cp.async.cg.shared.global [%0], [%1], 16;" :: "r"(dst), "l"(src));
}
#define CP_COMMIT() asm volatile("cp.async.commit_group;" ::: "memory")
#define CP_WAIT0()  asm volatile("cp.async.wait_group 0;" ::: "memory")
#define CP_WAIT1()  asm volatile("cp.async.wait_group 1;" ::: "memory")

__device__ __forceinline__ uint32_t sw128(uint32_t off) {
    return off ^ ((off >> 3) & 0x70);
}
__device__ __forceinline__ void ldmat_x4(uint32_t* r, uint32_t addr) {
    asm volatile("ldmatrix.sync.aligned.m8n8.x4.shared.b16 {%0,%1,%2,%3}, [%4];"
        : "=r"(r[0]), "=r"(r[1]), "=r"(r[2]), "=r"(r[3]) : "r"(addr));
}
__device__ __forceinline__ void imma16832(int* c, const uint32_t* a, const uint32_t* b) {
    asm volatile("mma.sync.aligned.m16n8k32.row.col.s32.s8.s8.s32 "
        "{%0,%1,%2,%3}, {%4,%5,%6,%7}, {%8,%9}, {%0,%1,%2,%3};"
        : "+r"(c[0]), "+r"(c[1]), "+r"(c[2]), "+r"(c[3])
        : "r"(a[0]), "r"(a[1]), "r"(a[2]), "r"(a[3]), "r"(b[0]), "r"(b[1]));
}
__device__ __forceinline__ int8_t q8(float v, float rq) {
    int q = __float2int_rn(v * rq);
    q = max(-127, min(127, q));
    return (int8_t)q;
}

// ---------------- kernel 1: normalize patches + reset state ----------------
__global__ void norm_patches_kernel(const float* __restrict__ tokens) {
    int pb = blockIdx.x, tid = threadIdx.x;
    if (tid == 0) {
        g_maxq[pb] = 0u;
        if (pb < NP) g_cnt[pb] = 0;
    }
    int8_t* dst8 = g_pA8 + (size_t)pb * D_;
    if (pb >= NP) {
        dst8[tid] = 0; dst8[tid + 256] = 0; dst8[tid + 512] = 0;
        if (tid == 0) g_sa[pb] = 0.0f;
        return;
    }
    int b = pb / P_PER_B, j = pb % P_PER_B;
    const float* src = tokens + ((size_t)(b * TOK + 1 + j)) * D_;
    float v0 = src[tid], v1 = src[tid + 256], v2 = src[tid + 512];
    float s = v0 * v0 + v1 * v1 + v2 * v2;
    float a = fmaxf(fabsf(v0), fmaxf(fabsf(v1), fabsf(v2)));

    __shared__ float ws[8], wa[8];
    __shared__ float s_tot, s_amax;
    #pragma unroll
    for (int o = 16; o; o >>= 1) {
        s += __shfl_xor_sync(0xFFFFFFFFu, s, o);
        a = fmaxf(a, __shfl_xor_sync(0xFFFFFFFFu, a, o));
    }
    if ((tid & 31) == 0) { ws[tid >> 5] = s; wa[tid >> 5] = a; }
    __syncthreads();
    if (tid < 32) {
        float t = (tid < 8) ? ws[tid] : 0.0f;
        float m = (tid < 8) ? wa[tid] : 0.0f;
        #pragma unroll
        for (int o = 4; o; o >>= 1) {
            t += __shfl_xor_sync(0xFFFFFFFFu, t, o);
            m = fmaxf(m, __shfl_xor_sync(0xFFFFFFFFu, m, o));
        }
        if (tid == 0) { s_tot = t; s_amax = m; }
    }
    __syncthreads();
    float tot = s_tot;
    float inv = 1.0f / (sqrtf(tot) + 1e-12f);
    float amax_n = s_amax * inv;
    float rq = (amax_n > 0.0f) ? (127.0f / amax_n) : 0.0f;

    float* pn = g_pN + (size_t)pb * D_;
    float n0 = v0 * inv, n1 = v1 * inv, n2 = v2 * inv;
    pn[tid] = n0; pn[tid + 256] = n1; pn[tid + 512] = n2;
    dst8[tid]       = q8(n0, rq);
    dst8[tid + 256] = q8(n1, rq);
    dst8[tid + 512] = q8(n2, rq);
    if (tid == 0) {
        g_sa[pb] = amax_n / 127.0f;
        g_p2[pb] = tot * inv * inv;
    }
}

// ---------------- kernel 2: MB stats + int8 quantize ------------------------
__global__ void mb_convert_kernel(const float* __restrict__ mb) {
    int row  = blockIdx.x * 8 + (threadIdx.x >> 5);
    int lane = threadIdx.x & 31;
    if (row >= NM_PAD) return;
    uint32_t* dst = (uint32_t*)(g_mbB8 + (size_t)row * D_);
    if (row < NM) {
        const float4* r = (const float4*)(mb + (size_t)row * D_);
        float4 v[6]; float s = 0.0f, a = 0.0f;
        #pragma unroll
        for (int i = 0; i < 6; i++) {
            v[i] = r[lane + i * 32];
            s += v[i].x * v[i].x + v[i].y * v[i].y + v[i].z * v[i].z + v[i].w * v[i].w;
            a = fmaxf(a, fmaxf(fmaxf(fabsf(v[i].x), fabsf(v[i].y)),
                               fmaxf(fabsf(v[i].z), fabsf(v[i].w))));
        }
        #pragma unroll
        for (int o = 16; o; o >>= 1) {
            s += __shfl_xor_sync(0xFFFFFFFFu, s, o);
            a = fmaxf(a, __shfl_xor_sync(0xFFFFFFFFu, a, o));
        }
        float rq = (a > 0.0f) ? (127.0f / a) : 0.0f;
        #pragma unroll
        for (int i = 0; i < 6; i++) {
            uint32_t w = ((uint32_t)(uint8_t)q8(v[i].x, rq))
                       | ((uint32_t)(uint8_t)q8(v[i].y, rq) << 8)
                       | ((uint32_t)(uint8_t)q8(v[i].z, rq) << 16)
                       | ((uint32_t)(uint8_t)q8(v[i].w, rq) << 24);
            dst[lane + i * 32] = w;
        }
        if (lane == 0) {
            float inv = 1.0f / (sqrtf(s) + 1e-12f);
            g_inv[row]  = inv;
            g_bias[row] = 0.5f * s * inv * inv;
            g_c1[row]   = (a / 127.0f) * inv;
        }
    } else {
        #pragma unroll
        for (int i = 0; i < 6; i++) dst[lane + i * 32] = 0u;
        if (lane == 0) { g_inv[row] = 0.0f; g_bias[row] = 1e30f; g_c1[row] = 0.0f; }
    }
}

// ---------------- kernel 3: IMMA GEMM + pre-gated per-column append ---------
__global__ void __launch_bounds__(NTHR, 2)
gemm_imma_kernel() {
    extern __shared__ __align__(1024) char smem[];
    const uint32_t sbase = smem_u32(smem);
    const int tid  = threadIdx.x;
    const int wid  = tid >> 5;
    const int lane = tid & 31;
    const int p0 = blockIdx.x * BM;
    const int n0 = blockIdx.y * BN;
    const int wm = (wid & 1) * 64;
    const int wn_idx = wid >> 1;
    const int wn = wn_idx * 32;
    const int g  = lane >> 2;
    const int tq = lane & 3;

    float* sa_s   = (float*)(smem + SM_SA);
    float* c1_s   = (float*)(smem + SM_C1);
    float* bias_s = (float*)(smem + SM_BIAS);
    uint32_t* red = (uint32_t*)(smem + SM_RED);    // [128 rows][4 groups]
    float* gate_s = (float*)(smem + SM_GATE);      // [128 rows]

    if (tid < 128) {
        sa_s[tid]   = g_sa[p0 + tid];
        c1_s[tid]   = g_c1[n0 + tid];
        bias_s[tid] = g_bias[n0 + tid];
    }

    const int8_t* gA = g_pA8  + (size_t)p0 * D_;
    const int8_t* gB = g_mbB8 + (size_t)n0 * D_;
    const int ld_r = tid >> 3;
    const int ld_c = tid & 7;
    const uint32_t ld_off0 = sw128((uint32_t)(ld_r * 128 + ld_c * 16));
    const uint32_t ld_off1 = sw128((uint32_t)((ld_r + 32) * 128 + ld_c * 16));
    const uint32_t ld_off2 = sw128((uint32_t)((ld_r + 64) * 128 + ld_c * 16));
    const uint32_t ld_off3 = sw128((uint32_t)((ld_r + 96) * 128 + ld_c * 16));

    // prologue: chunks 0,1 -> stages 0,1
    #pragma unroll
    for (int pc = 0; pc < 2; pc++) {
        const int8_t* cA = gA + (size_t)pc * KCB;
        const int8_t* cB = gB + (size_t)pc * KCB;
        const uint32_t dA = sbase + SM_A(pc);
        const uint32_t dB = sbase + SM_B(pc);
        const size_t ga0 = (size_t)ld_r * D_ + ld_c * 16;
        cp_async16(dA + ld_off0, cA + ga0);
        cp_async16(dA + ld_off1, cA + ga0 + (size_t)32 * D_);
        cp_async16(dA + ld_off2, cA + ga0 + (size_t)64 * D_);
        cp_async16(dA + ld_off3, cA + ga0 + (size_t)96 * D_);
        cp_async16(dB + ld_off0, cB + ga0);
        cp_async16(dB + ld_off1, cB + ga0 + (size_t)32 * D_);
        cp_async16(dB + ld_off2, cB + ga0 + (size_t)64 * D_);
        cp_async16(dB + ld_off3, cB + ga0 + (size_t)96 * D_);
        CP_COMMIT();
    }

    const uint32_t aRow = (uint32_t)(wm + (lane & 15)) * 128;
    const uint32_t aCol = (uint32_t)((lane >> 4) << 4);
    const uint32_t bRow = (uint32_t)(wn + (lane & 7) + ((lane >> 4) << 3)) * 128;
    const uint32_t bCol = (uint32_t)(((lane >> 3) & 1) << 4);

    int acc[4][4][4];
    #pragma unroll
    for (int i = 0; i < 4; i++)
        #pragma unroll
        for (int j = 0; j < 4; j++)
            #pragma unroll
            for (int q = 0; q < 4; q++) acc[i][j][q] = 0;

    #pragma unroll 1
    for (int kc = 0; kc < NCHUNK; kc++) {
        const int s = kc % 3;
        const uint32_t sA = sbase + SM_A(s);
        const uint32_t sB = sbase + SM_B(s);

        if (kc + 1 < NCHUNK) { CP_WAIT1(); } else { CP_WAIT0(); }
        __syncthreads();

        if (kc + 2 < NCHUNK) {
            const int d = (kc + 2) % 3;
            const uint32_t dA = sbase + SM_A(d);
            const uint32_t dB = sbase + SM_B(d);
            const int8_t* cA = gA + (size_t)(kc + 2) * KCB;
            const int8_t* cB = gB + (size_t)(kc + 2) * KCB;
            const size_t ga0 = (size_t)ld_r * D_ + ld_c * 16;
            cp_async16(dA + ld_off0, cA + ga0);
            cp_async16(dA + ld_off1, cA + ga0 + (size_t)32 * D_);
            cp_async16(dA + ld_off2, cA + ga0 + (size_t)64 * D_);
            cp_async16(dA + ld_off3, cA + ga0 + (size_t)96 * D_);
            cp_async16(dB + ld_off0, cB + ga0);
            cp_async16(dB + ld_off1, cB + ga0 + (size_t)32 * D_);
            cp_async16(dB + ld_off2, cB + ga0 + (size_t)64 * D_);
            cp_async16(dB + ld_off3, cB + ga0 + (size_t)96 * D_);
            CP_COMMIT();
        }

        #pragma unroll
        for (int ks = 0; ks < 4; ks++) {
            const uint32_t kb = (uint32_t)(ks * 32);
            uint32_t af[4][4], bf[2][4];
            #pragma unroll
            for (int tm = 0; tm < 4; tm++)
                ldmat_x4(af[tm], sA + sw128(aRow + (uint32_t)(tm * 16 * 128) + kb + aCol));
            #pragma unroll
            for (int bn = 0; bn < 2; bn++)
                ldmat_x4(bf[bn], sB + sw128(bRow + (uint32_t)(bn * 16 * 128) + kb + bCol));
            #pragma unroll
            for (int tm = 0; tm < 4; tm++)
                #pragma unroll
                for (int tn = 0; tn < 4; tn++)
                    imma16832(acc[tm][tn], af[tm], bf[tn >> 1] + (tn & 1) * 2);
        }
    }
    __syncthreads();

    // ---- epilogue phase 1: per-row max (value only) ----
    #pragma unroll
    for (int tm = 0; tm < 4; tm++) {
        #pragma unroll
        for (int half = 0; half < 2; half++) {
            int rl = wm + tm * 16 + g + half * 8;
            float sar = sa_s[rl];
            float best = -3.0e38f;
            #pragma unroll
            for (int tn = 0; tn < 4; tn++) {
                int cl = wn + tn * 8 + tq * 2;
                float v0 = (float)acc[tm][tn][half * 2 + 0] * (sar * c1_s[cl])     - bias_s[cl];
                float v1 = (float)acc[tm][tn][half * 2 + 1] * (sar * c1_s[cl + 1]) - bias_s[cl + 1];
                best = fmaxf(best, fmaxf(v0, v1));
            }
            best = fmaxf(best, __shfl_xor_sync(0xFFFFFFFFu, best, 1));
            best = fmaxf(best, __shfl_xor_sync(0xFFFFFFFFu, best, 2));
            if (tq == 0) red[rl * 4 + wn_idx] = enc(best);
        }
    }
    __syncthreads();

    // per-row: ONE atomicMax; publish gate value for phase 2
    if (tid < 128) {
        int p = p0 + tid;
        float gatev = 3.0e38f;           // padding rows: gate passes nothing
        if (p < NP) {
            uint32_t k0 = red[tid * 4 + 0];
            uint32_t k1 = red[tid * 4 + 1];
            uint32_t k2 = red[tid * 4 + 2];
            uint32_t k3 = red[tid * 4 + 3];
            uint32_t rowmax = max(max(k0, k1), max(k2, k3));
            uint32_t old = atomicMax(&g_maxq[p], rowmax);
            gatev = dec(max(old, rowmax)) - MARGIN;
        }
        gate_s[tid] = gatev;
    }
    __syncthreads();

    // ---- epilogue phase 2: group-key pre-gate, then per-column append ------
    // red[rl*4+wn_idx] bounds every column value this thread holds for row rl;
    // recompute + append only when the group can contain a candidate (rare).
    #pragma unroll
    for (int tm = 0; tm < 4; tm++) {
        #pragma unroll
        for (int half = 0; half < 2; half++) {
            int rl = wm + tm * 16 + g + half * 8;
            float gate = gate_s[rl];
            if (dec(red[rl * 4 + wn_idx]) >= gate) {   // group pre-gate (rare)
                float sar = sa_s[rl];
                int p = p0 + rl;
                #pragma unroll
                for (int tn = 0; tn < 4; tn++) {
                    int cl = wn + tn * 8 + tq * 2;
                    float v0 = (float)acc[tm][tn][half * 2 + 0] * (sar * c1_s[cl])     - bias_s[cl];
                    float v1 = (float)acc[tm][tn][half * 2 + 1] * (sar * c1_s[cl + 1]) - bias_s[cl + 1];
                    if (v0 >= gate) {
                        int ix = atomicAdd(&g_cnt[p], 1);
                        if (ix < CAP)
                            g_list[(size_t)p * CAP + ix] =
                                ((unsigned long long)enc(v0) << 32) | (uint32_t)(n0 + cl);
                    }
                    if (v1 >= gate) {
                        int ix = atomicAdd(&g_cnt[p], 1);
                        if (ix < CAP)
                            g_list[(size_t)p * CAP + ix] =
                                ((unsigned long long)enc(v1) << 32) | (uint32_t)(n0 + cl + 1);
                    }
                }
            }
        }
    }
}

// ---------------- kernel 4: rescore — exact fp32 on listed columns ----------
__global__ void __launch_bounds__(128)
rescore_kernel(const float* __restrict__ mb) {
    __shared__ int s_cols[64];
    __shared__ int s_ccnt;
    __shared__ float s_best[4];

    const int p = blockIdx.x;
    const int tid = threadIdx.x;
    const int wid = tid >> 5;
    const int lane = tid & 31;

    const float thr = dec(g_maxq[p]) - MARGIN;
    const uint32_t thrkey = enc(thr);
    const int cnt = g_cnt[p];
    const bool overflow = (cnt > CAP);
    if (tid == 0) s_ccnt = 0;
    __syncthreads();

    if (!overflow) {
        const unsigned long long* lst = g_list + (size_t)p * CAP;
        for (int e = tid; e < cnt; e += 128) {
            unsigned long long v = lst[e];
            if ((uint32_t)(v >> 32) >= thrkey) {
                int ix = atomicAdd(&s_ccnt, 1);
                if (ix < 64) s_cols[ix] = (int)(uint32_t)v;
            }
        }
        __syncthreads();
    } else {
        // fallback (statistically never): dp4a full scan over all columns
        const float sa = g_sa[p];
        int paw[6];
        const int* pa = (const int*)(g_pA8 + (size_t)p * D_);
        #pragma unroll
        for (int i = 0; i < 6; i++) paw[i] = pa[lane + i * 32];
        for (int base = wid * 8; base < NGRP * 32; base += 32) {
            int acc8[8]; int col8[8];
            #pragma unroll
            for (int j = 0; j < 8; j++) {
                int idx = base + j;
                col8[j] = idx;
                acc8[j] = 0;
                const int* bc = (const int*)(g_mbB8 + (size_t)idx * D_);
                #pragma unroll
                for (int i = 0; i < 6; i++)
                    acc8[j] = __dp4a(paw[i], bc[lane + i * 32], acc8[j]);
            }
            #pragma unroll
            for (int j = 0; j < 8; j++) {
                int dot = __reduce_add_sync(0xFFFFFFFFu, acc8[j]);
                if (lane == 0) {
                    int col = col8[j];
                    float vq = (float)dot * sa * g_c1[col] - g_bias[col];
                    if (vq >= thr) {
                        int ix = atomicAdd(&s_ccnt, 1);
                        if (ix < 64) s_cols[ix] = col;
                    }
                }
            }
        }
        __syncthreads();
    }
    const int nc = min(s_ccnt, 64);

    // exact fp32 rescore of surviving columns (warp per column)
    float pnw[24];
    {
        const float* pn = g_pN + (size_t)p * D_;
        #pragma unroll
        for (int i = 0; i < 24; i++) pnw[i] = pn[lane + i * 32];
    }
    float bestE = -3.0e38f;
    for (int ic = wid; ic < nc; ic += 4) {
        int col = s_cols[ic];
        const float* mcol = mb + (size_t)col * D_;
        float dot = 0.0f;
        #pragma unroll
        for (int i = 0; i < 24; i++) dot += pnw[i] * mcol[lane + i * 32];
        #pragma unroll
        for (int o = 16; o; o >>= 1) dot += __shfl_xor_sync(0xFFFFFFFFu, dot, o);
        bestE = fmaxf(bestE, dot * g_inv[col] - g_bias[col]);
    }
    if (lane == 0) s_best[wid] = bestE;
    __syncthreads();
    if (tid == 0) {
        float m = fmaxf(fmaxf(s_best[0], s_best[1]), fmaxf(s_best[2], s_best[3]));
        g_maxv[p] = f2ord(m);
    }
}

// ---------------- kernel 5: finalize ----------------------------------------
__global__ void finalize_kernel(float* __restrict__ out) {
    int b = threadIdx.x;
    if (b >= B_) return;
    float mx = -3.0e38f;
    #pragma unroll 7
    for (int j = 0; j < P_PER_B; j++) {
        int p = b * P_PER_B + j;
        float v  = ord2f(g_maxv[p]);
        float d2 = g_p2[p] - 2.0f * v;
        mx = fmaxf(mx, d2);
    }
    out[b] = sqrtf(fmaxf(mx, 1e-12f));
}

// ---------------- launch -----------------------------------------------------
extern "C" void kernel_launch(void* const* d_in, const int* in_sizes, int n_in,
                              void* d_out, int out_size) {
    (void)in_sizes; (void)n_in; (void)out_size;
    const float* tokens = (const float*)d_in[0];
    const float* mb     = (const float*)d_in[1];
    float* out          = (float*)d_out;

    norm_patches_kernel<<<NP_PAD, 256>>>(tokens);
    mb_convert_kernel<<<NM_PAD / 8, 256>>>(mb);

    cudaFuncSetAttribute(gemm_imma_kernel,
                         cudaFuncAttributeMaxDynamicSharedMemorySize, SM_TOTAL);
    dim3 grid(NP_PAD / BM, NM_PAD / BN);   // (25, 782)
    gemm_imma_kernel<<<grid, NTHR, SM_TOTAL>>>();

    rescore_kernel<<<NP, 128>>>(mb);
    finalize_kernel<<<1, 64>>>(out);
}